// round 11
// baseline (speedup 1.0000x reference)
#include <cuda_runtime.h>
#include <cstdint>

// Problem constants
#define NN 8
#define CC 128
#define HH 56
#define WW 56
#define COo 16
#define HWSZ (HH*WW)

// Conv tiling
#define S_SPLIT 16           // K-split over channels (16 tiles of 8 channels)
#define KC (CC/S_SPLIT)      // 8 channels per tile
#define KCS 4                // channels per smem chunk
#define TH 8                 // output rows per tile
#define TROWS (TH+8)         // input rows incl. halo (dilation 2 * (5-1) = 8)
#define TCOLS (WW+18)        // input cols incl. halo (dilation 3 * (7-1) = 18) = 74
#define TCSTRIDE 92          // 92 % 32 == 28 -> warp-spanning lanes hit disjoint banks
#define THREADS_A 224        // 8 rows * 28 wgroups = 7 full warps
#define NTILES (7*NN*S_SPLIT) // 896 tiles
#define OCC_A 4
#define GRID_A (148*OCC_A)   // 592 persistent blocks = one full wave at occ 4

// Split-K scratch: [S][N][CO][H*W]  (25.7 MB)
__device__ float g_ypart[S_SPLIT * NN * COo * HWSZ];
// Dynamic tile counter. Statically initialized for the first (correctness)
// call; the epilogue resets it after every conv pass so each graph replay
// sees the same starting value. Deterministic: tile->output mapping is
// disjoint regardless of which block executes which tile.
__device__ unsigned g_ctr = GRID_A;

__device__ __forceinline__ unsigned long long pack2(float x) {
    unsigned long long r;
    unsigned int xi = __float_as_uint(x);
    asm("mov.b64 %0, {%1, %1};" : "=l"(r) : "r"(xi));
    return r;
}
__device__ __forceinline__ unsigned long long ffma2(unsigned long long a,
                                                    unsigned long long b,
                                                    unsigned long long c) {
    unsigned long long d;
    asm("fma.rn.f32x2 %0, %1, %2, %3;" : "=l"(d) : "l"(a), "l"(b), "l"(c));
    return d;
}
__device__ __forceinline__ void unpack2(unsigned long long v, float& lo, float& hi) {
    unsigned int l, h;
    asm("mov.b64 {%0, %1}, %2;" : "=r"(l), "=r"(h) : "l"(v));
    lo = __uint_as_float(l);
    hi = __uint_as_float(h);
}

// ---------------------------------------------------------------------------
// Kernel A: dilated 5x7 conv (C->CO), split-K over 16 channel groups.
// Persistent blocks (592 = one full wave at occ 4) pull tiles dynamically.
// Each thread: 2 pixels (w, w+28) x 16 CO, accumulated as 16 f32x2 regs.
// ---------------------------------------------------------------------------
__global__ __launch_bounds__(THREADS_A, OCC_A)
void conv_partial_kernel(const float* __restrict__ x, const float* __restrict__ w3) {
    __shared__ float xs[KCS][TROWS][TCSTRIDE];
    __shared__ __align__(16) float ws[KCS][5][7][COo];   // [ci][kh][kw][o]
    __shared__ unsigned s_next;

    const int tid = threadIdx.x;
    const int r  = tid / 28;     // output row within tile, 0..7
    const int wg = tid % 28;     // first pixel column, 0..27 (second = wg+28)

    unsigned tile = blockIdx.x;

    while (tile < NTILES) {
        // tile -> (ht fastest for x L2 locality, then n, then s)
        const int ht = tile % 7;
        const int n  = (tile / 7) & (NN - 1);
        const int s  = tile / (7 * NN);
        const int h0 = ht * TH;
        const int cbase = s * KC;

        unsigned long long acc0[8], acc1[8];
#pragma unroll
        for (int j = 0; j < 8; j++) { acc0[j] = 0ull; acc1[j] = 0ull; }

#pragma unroll
        for (int cc = 0; cc < KC; cc += KCS) {
            __syncthreads();  // protect smem reuse from previous chunk's readers

            // --- stage weights first (few, unconditional LDGs issue early) ---
            for (int idx = tid; idx < KCS * 35 * COo; idx += THREADS_A) {
                int ci  = idx / (35 * COo);
                int rem = idx % (35 * COo);
                int t   = rem / COo;       // kh*7 + kw
                int o   = rem % COo;
                int c   = cbase + cc + ci;
                (&ws[0][0][0][0])[idx] = w3[((size_t)o * CC + c) * 35 + t];
            }
            // --- stage x tile: KCS channels x TROWS x TCOLS (zero-padded halo) ---
            for (int idx = tid; idx < KCS * TROWS * TCOLS; idx += THREADS_A) {
                int ci  = idx / (TROWS * TCOLS);
                int rem = idx % (TROWS * TCOLS);
                int tr  = rem / TCOLS;
                int tc  = rem % TCOLS;
                int h_in = h0 - 4 + tr;
                int w_in = tc - 9;
                float v = 0.0f;
                if ((unsigned)h_in < HH && (unsigned)w_in < WW)
                    v = x[(((size_t)n * CC + (cbase + cc + ci)) * HH + h_in) * WW + w_in];
                xs[ci][tr][tc] = v;
            }
            __syncthreads();

            // --- compute ---
#pragma unroll
            for (int ci = 0; ci < KCS; ci++) {
#pragma unroll
                for (int kh = 0; kh < 5; kh++) {
                    const float* xrow = &xs[ci][r + 2 * kh][0];
#pragma unroll
                    for (int kw = 0; kw < 7; kw++) {
                        float xa = xrow[wg + 3 * kw];
                        float xb = xrow[wg + 28 + 3 * kw];
                        unsigned long long xa2 = pack2(xa);
                        unsigned long long xb2 = pack2(xb);
                        const ulonglong2* wp = (const ulonglong2*)&ws[ci][kh][kw][0];
#pragma unroll
                        for (int q = 0; q < 4; q++) {
                            ulonglong2 wv = wp[q];
                            acc0[2*q]   = ffma2(xa2, wv.x, acc0[2*q]);
                            acc0[2*q+1] = ffma2(xa2, wv.y, acc0[2*q+1]);
                            acc1[2*q]   = ffma2(xb2, wv.x, acc1[2*q]);
                            acc1[2*q+1] = ffma2(xb2, wv.y, acc1[2*q+1]);
                        }
                    }
                }
            }
        }

        // --- store partials: g_ypart[s][n][o][h*56 + w] ---
        const int h = h0 + r;
        float* yp = &g_ypart[(((size_t)s * NN + n) * COo) * HWSZ + h * WW];
#pragma unroll
        for (int j = 0; j < 8; j++) {
            float lo, hi;
            unpack2(acc0[j], lo, hi);
            yp[(2*j)   * HWSZ + wg] = lo;
            yp[(2*j+1) * HWSZ + wg] = hi;
            unpack2(acc1[j], lo, hi);
            yp[(2*j)   * HWSZ + wg + 28] = lo;
            yp[(2*j+1) * HWSZ + wg + 28] = hi;
        }

        // --- fetch next tile (dynamic balancing) ---
        __syncthreads();   // all threads done reading s_next from prior round
        if (tid == 0) s_next = atomicAdd(&g_ctr, 1u);
        __syncthreads();
        tile = s_next;
    }
}

// ---------------------------------------------------------------------------
// Kernel B: reduce 16 split-K partials, apply w4 (16x16) then w5 (128x16).
// 448 blocks (one per (row, n)); 4 threads per pixel. Block 0 also resets the
// dynamic tile counter for the next graph replay.
// ---------------------------------------------------------------------------
__global__ __launch_bounds__(THREADS_A)
void epilogue_kernel(const float* __restrict__ w4, const float* __restrict__ w5,
                     float* __restrict__ out) {
    __shared__ float w4s[COo * COo];
    __shared__ float w5s[CC * COo];
    __shared__ float ysh[COo][4][57];   // [c][q][px], pad 57 to soften conflicts
    const int tid = threadIdx.x;

    // Reset conv's tile counter for the next replay (conv already finished).
    if (blockIdx.x == 0 && blockIdx.y == 0 && tid == 0) g_ctr = GRID_A;

    for (int i = tid; i < COo * COo; i += THREADS_A) w4s[i] = w4[i];
    for (int i = tid; i < CC * COo; i += THREADS_A) w5s[i] = w5[i];

    const int n  = blockIdx.y;
    const int h  = blockIdx.x;
    const int px = tid % 56;
    const int q  = tid / 56;          // 0..3
    const int p  = h * WW + px;
    __syncthreads();

    // partial reduction: each thread sums 4 of the 16 s-slices for all 16 c
#pragma unroll
    for (int c = 0; c < COo; c++) {
        float v = 0.0f;
#pragma unroll
        for (int ss = 0; ss < 4; ss++) {
            int s = q * 4 + ss;
            v += g_ypart[(((size_t)s * NN + n) * COo + c) * HWSZ + p];
        }
        ysh[c][q][px] = v;
    }
    __syncthreads();

    float y[COo];
#pragma unroll
    for (int c = 0; c < COo; c++)
        y[c] = ysh[c][0][px] + ysh[c][1][px] + ysh[c][2][px] + ysh[c][3][px];

    float z[COo];
#pragma unroll
    for (int j = 0; j < COo; j++) {
        float v = 0.0f;
#pragma unroll
        for (int c = 0; c < COo; c++) v += w4s[j * COo + c] * y[c];
        z[j] = v;
    }

    float* outp = out + ((size_t)n * CC) * HWSZ + p;
#pragma unroll 4
    for (int oo = 0; oo < 32; oo++) {
        int o = q * 32 + oo;
        float v = 0.0f;
#pragma unroll
        for (int j = 0; j < COo; j++) v += w5s[o * COo + j] * z[j];
        outp[(size_t)o * HWSZ] = v;
    }
}

// ---------------------------------------------------------------------------
extern "C" void kernel_launch(void* const* d_in, const int* in_sizes, int n_in,
                              void* d_out, int out_size) {
    const float* x  = (const float*)d_in[0];
    const float* w3 = (const float*)d_in[1];
    const float* w4 = (const float*)d_in[2];
    const float* w5 = (const float*)d_in[3];
    float* out = (float*)d_out;

    conv_partial_kernel<<<GRID_A, THREADS_A>>>(x, w3);  // 592 persistent blocks
    dim3 gridB(HH, NN);                                 // 56 x 8 = 448 blocks
    epilogue_kernel<<<gridB, THREADS_A>>>(w4, w5, out);
}

// round 12
// speedup vs baseline: 1.1428x; 1.1428x over previous
#include <cuda_runtime.h>
#include <cstdint>

// Problem constants
#define NN 8
#define CC 128
#define HH 56
#define WW 56
#define COo 16
#define HWSZ (HH*WW)

// Conv tiling
#define S_SPLIT 16           // K-split over channels (16 tiles of 8 channels)
#define KC (CC/S_SPLIT)      // 8 channels per tile
#define KCS 4                // channels per smem chunk (2 chunks per tile)
#define TH 8                 // output rows per tile
#define TROWS (TH+8)         // input rows incl. halo (dilation 2 * (5-1) = 8)
#define TCOLS (WW+18)        // input cols incl. halo = 74
#define TCSTRIDE 92          // 92 % 32 == 28 -> warp-spanning lanes hit disjoint banks
#define THREADS_A 256        // 8 warps: 7 compute warps (8 rows x 28 cols), all 8 stage
#define NTILES (7*NN*S_SPLIT) // 896 tiles
#define OCC_A 3
#define GRID_A (148*OCC_A)   // 444 persistent blocks = one full wave at occ 3
#define WCHUNK (KCS*35*COo)  // 2240 weight floats per chunk

// Split-K scratch: [S][N][CO][H*W]  (25.7 MB)
__device__ float g_ypart[S_SPLIT * NN * COo * HWSZ];
// Dynamic tile counter. Statically initialized for the first call; the
// epilogue resets it after every conv pass so each graph replay sees the
// same starting value. Tile->output mapping is disjoint -> deterministic.
__device__ unsigned g_ctr = GRID_A;

__device__ __forceinline__ unsigned long long pack2(float x) {
    unsigned long long r;
    unsigned int xi = __float_as_uint(x);
    asm("mov.b64 %0, {%1, %1};" : "=l"(r) : "r"(xi));
    return r;
}
__device__ __forceinline__ unsigned long long ffma2(unsigned long long a,
                                                    unsigned long long b,
                                                    unsigned long long c) {
    unsigned long long d;
    asm("fma.rn.f32x2 %0, %1, %2, %3;" : "=l"(d) : "l"(a), "l"(b), "l"(c));
    return d;
}
__device__ __forceinline__ void unpack2(unsigned long long v, float& lo, float& hi) {
    unsigned int l, h;
    asm("mov.b64 {%0, %1}, %2;" : "=r"(l), "=r"(h) : "l"(v));
    lo = __uint_as_float(l);
    hi = __uint_as_float(h);
}

// cp.async 4B with zero-fill: src_size = 4 (copy) or 0 (zfill, no mem access).
__device__ __forceinline__ void cp_async4(uint32_t dst_smem, const void* src, unsigned src_size) {
    asm volatile("cp.async.ca.shared.global [%0], [%1], 4, %2;\n"
                 :: "r"(dst_smem), "l"(src), "r"(src_size));
}
__device__ __forceinline__ void cp_commit() {
    asm volatile("cp.async.commit_group;\n");
}
template<int N>
__device__ __forceinline__ void cp_wait() {
    asm volatile("cp.async.wait_group %0;\n" :: "n"(N));
}

// ---------------------------------------------------------------------------
// Kernel A: dilated 5x7 conv (C->CO), split-K over 16 channel groups.
// Persistent blocks pull tiles dynamically; cp.async double-buffered staging
// (chunk1 of current tile and chunk0 of the NEXT tile prefetched under
// compute). 7 compute warps: 2 pixels (w, w+28) x 16 CO as 16 f32x2 regs.
// ---------------------------------------------------------------------------
__global__ __launch_bounds__(THREADS_A, OCC_A)
void conv_partial_kernel(const float* __restrict__ x, const float* __restrict__ w3) {
    __shared__ float xs[2][KCS][TROWS][TCSTRIDE];
    __shared__ __align__(16) float ws[2][KCS][5][7][COo];   // [buf][ci][kh][kw][o]
    __shared__ unsigned s_next;

    const int tid  = threadIdx.x;
    const int warp = tid >> 5;
    const int lane = tid & 31;
    const int r  = (tid < 224) ? tid / 28 : 0;   // compute row (warps 0..6)
    const int wg = (tid < 224) ? tid % 28 : 0;   // first pixel col (second = +28)

    const uint32_t xs_base = (uint32_t)__cvta_generic_to_shared(&xs[0][0][0][0]);
    const uint32_t ws_base = (uint32_t)__cvta_generic_to_shared(&ws[0][0][0][0]);

    // Staging row assignment: warp w covers rows [w*8, w*8+8) of 64 = KCS*TROWS.
    const int ci_s[8] = { (warp*8+0)>>4, (warp*8+1)>>4, (warp*8+2)>>4, (warp*8+3)>>4,
                          (warp*8+4)>>4, (warp*8+5)>>4, (warp*8+6)>>4, (warp*8+7)>>4 };
    const int tr_s[8] = { (warp*8+0)&15, (warp*8+1)&15, (warp*8+2)&15, (warp*8+3)&15,
                          (warp*8+4)&15, (warp*8+5)&15, (warp*8+6)&15, (warp*8+7)&15 };

    // Stage one KCS-channel chunk of x + weights into buffer `buf` (async).
    auto stage_chunk = [&](int buf, int n, int h0, int cbase_cc) {
        // x tile: coalesced, warp-per-rowgroup, lane covers cols in 3 passes.
#pragma unroll
        for (int rr = 0; rr < 8; rr++) {
            const int ci = ci_s[rr], tr = tr_s[rr];
            const int h_in = h0 - 4 + tr;
            const bool hok = (unsigned)h_in < HH;
            const float* rowp = x + (((size_t)n * CC + (cbase_cc + ci)) * HH + h_in) * WW;
            const uint32_t drow = xs_base + (((buf*KCS + ci)*TROWS + tr)*TCSTRIDE) * 4;
#pragma unroll
            for (int pass = 0; pass < 3; pass++) {
                int tc = lane + 32 * pass;
                if (tc < TCOLS) {
                    int w_in = tc - 9;
                    bool ok = hok && (unsigned)w_in < WW;
                    const float* src = ok ? (rowp + w_in) : x;  // safe addr when size=0
                    cp_async4(drow + tc * 4, src, ok ? 4u : 0u);
                }
            }
        }
        // weights, transposed to [ci][kh][kw][o]
#pragma unroll
        for (int i = 0; i < 9; i++) {
            int k = tid + i * THREADS_A;
            if (k < WCHUNK) {
                int ci  = k / (35 * COo);
                int rem = k % (35 * COo);
                int t   = rem >> 4;      // kh*7+kw
                int o   = rem & 15;
                const float* src = w3 + ((size_t)o * CC + (cbase_cc + ci)) * 35 + t;
                cp_async4(ws_base + (buf * WCHUNK + k) * 4, src, 4u);
            }
        }
    };

    // Compute one chunk from buffer `buf` into accumulators.
    unsigned long long acc0[8], acc1[8];
    auto compute_chunk = [&](int buf) {
        if (tid >= 224) return;
#pragma unroll
        for (int ci = 0; ci < KCS; ci++) {
#pragma unroll
            for (int kh = 0; kh < 5; kh++) {
                const float* xrow = &xs[buf][ci][r + 2 * kh][0];
#pragma unroll
                for (int kw = 0; kw < 7; kw++) {
                    float xa = xrow[wg + 3 * kw];
                    float xb = xrow[wg + 28 + 3 * kw];
                    unsigned long long xa2 = pack2(xa);
                    unsigned long long xb2 = pack2(xb);
                    const ulonglong2* wp = (const ulonglong2*)&ws[buf][ci][kh][kw][0];
#pragma unroll
                    for (int q = 0; q < 4; q++) {
                        ulonglong2 wv = wp[q];
                        acc0[2*q]   = ffma2(xa2, wv.x, acc0[2*q]);
                        acc0[2*q+1] = ffma2(xa2, wv.y, acc0[2*q+1]);
                        acc1[2*q]   = ffma2(xb2, wv.x, acc1[2*q]);
                        acc1[2*q+1] = ffma2(xb2, wv.y, acc1[2*q+1]);
                    }
                }
            }
        }
    };

    unsigned tile = blockIdx.x;
    int ht = tile % 7;
    int n  = (tile / 7) & (NN - 1);
    int s  = tile / (7 * NN);
    int h0 = ht * TH;
    int cbase = s * KC;

    // Prolog: stage chunk0 of first tile.
    stage_chunk(0, n, h0, cbase);
    cp_commit();                               // pending: {cur.c0}

    while (true) {
        // Prefetch chunk1 of current tile.
        stage_chunk(1, n, h0, cbase + KCS);
        cp_commit();                           // pending: {cur.c0, cur.c1}
        if (tid == 0) s_next = atomicAdd(&g_ctr, 1u);

#pragma unroll
        for (int j = 0; j < 8; j++) { acc0[j] = 0ull; acc1[j] = 0ull; }

        cp_wait<1>();                          // cur.c0 landed
        __syncthreads();
        compute_chunk(0);
        __syncthreads();                       // buf0 free; s_next visible

        unsigned nt = s_next;
        bool have_next = nt < NTILES;
        int nht = 0, nn = 0, nh0 = 0, ncb = 0;
        if (have_next) {
            nht = nt % 7; nn = (nt / 7) & (NN - 1);
            nh0 = nht * TH; ncb = (nt / (7 * NN)) * KC;
            stage_chunk(0, nn, nh0, ncb);      // prefetch next tile's chunk0
            cp_commit();                       // pending: {cur.c1, next.c0}
            cp_wait<1>();                      // cur.c1 landed
        } else {
            cp_wait<0>();
        }
        __syncthreads();
        compute_chunk(1);

        // Store partials: g_ypart[s][n][o][h*56 + w]
        if (tid < 224) {
            const int h = h0 + r;
            float* yp = &g_ypart[(((size_t)s * NN + n) * COo) * HWSZ + h * WW];
#pragma unroll
            for (int j = 0; j < 8; j++) {
                float lo, hi;
                unpack2(acc0[j], lo, hi);
                yp[(2*j)   * HWSZ + wg] = lo;
                yp[(2*j+1) * HWSZ + wg] = hi;
                unpack2(acc1[j], lo, hi);
                yp[(2*j)   * HWSZ + wg + 28] = lo;
                yp[(2*j+1) * HWSZ + wg + 28] = hi;
            }
        }

        if (!have_next) break;
        tile = nt; n = nn; h0 = nh0; cbase = ncb; s = nt / (7 * NN);
        __syncthreads();   // everyone done reading buf1 before it's re-staged
    }
}

// ---------------------------------------------------------------------------
// Kernel B: reduce 16 split-K partials, apply w4 (16x16) then w5 (128x16).
// Grid (56, 8, 2): z selects a 64-channel half of the 128 outputs -> 896
// blocks (fixes the grid-limited 30% occupancy). 4 threads per pixel.
// ---------------------------------------------------------------------------
__global__ __launch_bounds__(224)
void epilogue_kernel(const float* __restrict__ w4, const float* __restrict__ w5,
                     float* __restrict__ out) {
    __shared__ float w4s[COo * COo];
    __shared__ float w5s[(CC/2) * COo];
    __shared__ float ysh[COo][4][57];   // [c][q][px]
    const int tid = threadIdx.x;
    const int zh  = blockIdx.z;         // output-channel half

    // Reset conv's tile counter for the next replay (conv already finished).
    if (blockIdx.x == 0 && blockIdx.y == 0 && zh == 0 && tid == 0) g_ctr = GRID_A;

    for (int i = tid; i < COo * COo; i += 224) w4s[i] = w4[i];
    for (int i = tid; i < (CC/2) * COo; i += 224) w5s[i] = w5[zh * (CC/2) * COo + i];

    const int n  = blockIdx.y;
    const int h  = blockIdx.x;
    const int px = tid % 56;
    const int q  = tid / 56;          // 0..3
    const int p  = h * WW + px;
    __syncthreads();

    // partial reduction: each thread sums 4 of the 16 s-slices for all 16 c
#pragma unroll
    for (int c = 0; c < COo; c++) {
        float v = 0.0f;
#pragma unroll
        for (int ss = 0; ss < 4; ss++) {
            int s = q * 4 + ss;
            v += g_ypart[(((size_t)s * NN + n) * COo + c) * HWSZ + p];
        }
        ysh[c][q][px] = v;
    }
    __syncthreads();

    float y[COo];
#pragma unroll
    for (int c = 0; c < COo; c++)
        y[c] = ysh[c][0][px] + ysh[c][1][px] + ysh[c][2][px] + ysh[c][3][px];

    float z[COo];
#pragma unroll
    for (int j = 0; j < COo; j++) {
        float v = 0.0f;
#pragma unroll
        for (int c = 0; c < COo; c++) v += w4s[j * COo + c] * y[c];
        z[j] = v;
    }

    float* outp = out + (((size_t)n * CC) + zh * (CC/2)) * HWSZ + p;
#pragma unroll 4
    for (int oo = 0; oo < 16; oo++) {
        int o = q * 16 + oo;
        float v = 0.0f;
#pragma unroll
        for (int j = 0; j < COo; j++) v += w5s[o * COo + j] * z[j];
        outp[(size_t)o * HWSZ] = v;
    }
}

// ---------------------------------------------------------------------------
extern "C" void kernel_launch(void* const* d_in, const int* in_sizes, int n_in,
                              void* d_out, int out_size) {
    const float* x  = (const float*)d_in[0];
    const float* w3 = (const float*)d_in[1];
    const float* w4 = (const float*)d_in[2];
    const float* w5 = (const float*)d_in[3];
    float* out = (float*)d_out;

    conv_partial_kernel<<<GRID_A, THREADS_A>>>(x, w3);  // 444 persistent blocks
    dim3 gridB(HH, NN, 2);                              // 896 blocks
    epilogue_kernel<<<gridB, 224>>>(w4, w5, out);
}

// round 13
// speedup vs baseline: 1.2312x; 1.0774x over previous
#include <cuda_runtime.h>
#include <cstdint>

// Problem constants
#define NN 8
#define CC 128
#define HH 56
#define WW 56
#define COo 16
#define HWSZ (HH*WW)

// Conv tiling
#define S_SPLIT 16           // K-split over channels (16 tiles of 8 channels)
#define KC (CC/S_SPLIT)      // 8 channels per tile
#define KCS 4                // channels per smem chunk (2 chunks per tile)
#define TH 8                 // output rows per tile
#define TROWS (TH+8)         // input rows incl. halo (dilation 2 * (5-1) = 8)
#define XCOLS 80             // staged cols: w_in in [-12, 68) (16B-aligned window)
#define TCSTRIDE 92          // 92 % 32 == 28 -> warp-spanning lanes hit disjoint banks
#define THREADS_A 256        // 8 warps: 7 compute warps (8 rows x 28 cols), all 8 stage
#define NTILES (7*NN*S_SPLIT) // 896 tiles
#define OCC_A 3
#define GRID_A (148*OCC_A)   // 444 persistent blocks = one full wave at occ 3
#define WCHUNK (KCS*35*COo)  // 2240 weight floats per chunk = 560 uint4

// Split-K scratch: [S][N][CO][H*W]  (25.7 MB)
__device__ float g_ypart[S_SPLIT * NN * COo * HWSZ];
// Transposed conv weights: wT[c][t][o] (o contiguous) -> contiguous per chunk.
__device__ __align__(16) float g_wT[CC * 35 * COo];
// Fused epilogue weights: W = w5 @ w4, [o][j] (128 x 16).
__device__ float g_W[CC * COo];
// Dynamic tile counter (reset by prep_kernel each replay; static init covers
// nothing-before-prep since prep always precedes conv in the stream).
__device__ unsigned g_ctr = GRID_A;

__device__ __forceinline__ unsigned long long pack2(float x) {
    unsigned long long r;
    unsigned int xi = __float_as_uint(x);
    asm("mov.b64 %0, {%1, %1};" : "=l"(r) : "r"(xi));
    return r;
}
__device__ __forceinline__ unsigned long long ffma2(unsigned long long a,
                                                    unsigned long long b,
                                                    unsigned long long c) {
    unsigned long long d;
    asm("fma.rn.f32x2 %0, %1, %2, %3;" : "=l"(d) : "l"(a), "l"(b), "l"(c));
    return d;
}
__device__ __forceinline__ void unpack2(unsigned long long v, float& lo, float& hi) {
    unsigned int l, h;
    asm("mov.b64 {%0, %1}, %2;" : "=r"(l), "=r"(h) : "l"(v));
    lo = __uint_as_float(l);
    hi = __uint_as_float(h);
}

// 16B cp.async with zero-fill (src_size = 16 copies, 0 zero-fills).
__device__ __forceinline__ void cp_async16(uint32_t dst_smem, const void* src, unsigned src_size) {
    asm volatile("cp.async.cg.shared.global [%0], [%1], 16, %2;\n"
                 :: "r"(dst_smem), "l"(src), "r"(src_size));
}
__device__ __forceinline__ void cp_commit() {
    asm volatile("cp.async.commit_group;\n");
}
template<int N>
__device__ __forceinline__ void cp_wait() {
    asm volatile("cp.async.wait_group %0;\n" :: "n"(N));
}

// ---------------------------------------------------------------------------
// Prep kernel: (a) transpose w3 [o][c][t] -> wT [c][t][o] so conv can stage
// weights as contiguous 16B vectors; (b) W = w5 @ w4; (c) reset tile counter.
// Grid 144 x 512: blocks 0..139 do wT (exactly 71680), 140..143 do W (2048).
// ---------------------------------------------------------------------------
__global__ __launch_bounds__(512)
void prep_kernel(const float* __restrict__ w3, const float* __restrict__ w4,
                 const float* __restrict__ w5) {
    if (blockIdx.x == 0 && threadIdx.x == 0) g_ctr = GRID_A;
    int b = blockIdx.x;
    if (b < 140) {
        int idx = b * 512 + threadIdx.x;      // 0..71679
        int o  = idx & 15;
        int ct = idx >> 4;                    // c*35 + t
        int c  = ct / 35;
        int t  = ct % 35;
        g_wT[idx] = w3[((size_t)o * CC + c) * 35 + t];
    } else {
        int e = (b - 140) * 512 + threadIdx.x; // 0..2047
        int o = e >> 4, j = e & 15;
        float v = 0.0f;
#pragma unroll
        for (int c = 0; c < COo; c++) v += w5[o * COo + c] * w4[c * COo + j];
        g_W[e] = v;
    }
}

// ---------------------------------------------------------------------------
// Kernel A: dilated 5x7 conv (C->CO), split-K over 16 channel groups.
// Persistent blocks pull tiles dynamically; 16B cp.async double-buffered
// staging. 7 compute warps: 2 pixels (w, w+28) x 16 CO as 16 f32x2 regs.
// ---------------------------------------------------------------------------
__global__ __launch_bounds__(THREADS_A, OCC_A)
void conv_partial_kernel(const float* __restrict__ x) {
    __shared__ __align__(16) float xs[2][KCS][TROWS][TCSTRIDE];
    __shared__ __align__(16) float ws[2][KCS][5][7][COo];   // [buf][ci][kh][kw][o]
    __shared__ unsigned s_next;

    const int tid  = threadIdx.x;
    const int r  = (tid < 224) ? tid / 28 : 0;   // compute row (warps 0..6)
    const int wg = (tid < 224) ? tid % 28 : 0;   // first pixel col (second = +28)

    const uint32_t xs_base = (uint32_t)__cvta_generic_to_shared(&xs[0][0][0][0]);
    const uint32_t ws_base = (uint32_t)__cvta_generic_to_shared(&ws[0][0][0][0]);

    // Stage one KCS-channel chunk of x + weights into buffer `buf` (async).
    // x: 64 rows (4 ch x 16 tr) x 20 16B-vectors, window w_in = -12..67.
    // Every vector is 16B-aligned in gmem (row bases are 224B-aligned).
    auto stage_chunk = [&](int buf, int n, int h0, int cbase_cc) {
#pragma unroll
        for (int i = 0; i < 5; i++) {
            int idx = tid + i * THREADS_A;       // 0..1279
            int row = idx / 20;                  // 0..63
            int v   = idx % 20;                  // vector within row
            int ci  = row >> 4;
            int tr  = row & 15;
            int h_in = h0 - 4 + tr;
            int w0   = v * 4 - 12;               // first w_in of this vector
            bool ok = ((unsigned)h_in < HH) & (w0 >= 0) & (w0 + 3 < WW);
            const float* src = ok
                ? x + (((size_t)n * CC + (cbase_cc + ci)) * HH + h_in) * WW + w0
                : x;                             // valid addr; size=0 -> zfill
            uint32_t dst = xs_base +
                (((buf * KCS + ci) * TROWS + tr) * TCSTRIDE + v * 4) * 4;
            cp_async16(dst, src, ok ? 16u : 0u);
        }
        // weights: contiguous 560 uint4 from wT (layout matches ws exactly)
        const float* wsrc = g_wT + (size_t)cbase_cc * 35 * COo;
        uint32_t wdst = ws_base + (buf * WCHUNK) * 4;
#pragma unroll
        for (int i = 0; i < 3; i++) {
            int k = tid + i * THREADS_A;
            if (k < WCHUNK / 4)
                cp_async16(wdst + k * 16, wsrc + k * 4, 16u);
        }
    };

    unsigned long long acc0[8], acc1[8];
    auto compute_chunk = [&](int buf) {
        if (tid >= 224) return;
#pragma unroll
        for (int ci = 0; ci < KCS; ci++) {
#pragma unroll
            for (int kh = 0; kh < 5; kh++) {
                const float* xrow = &xs[buf][ci][r + 2 * kh][0];
#pragma unroll
                for (int kw = 0; kw < 7; kw++) {
                    // staged col = w_in + 12; needed w_in = w - 9 + 3kw
                    float xa = xrow[wg + 3 * kw + 3];
                    float xb = xrow[wg + 28 + 3 * kw + 3];
                    unsigned long long xa2 = pack2(xa);
                    unsigned long long xb2 = pack2(xb);
                    const ulonglong2* wp = (const ulonglong2*)&ws[buf][ci][kh][kw][0];
#pragma unroll
                    for (int q = 0; q < 4; q++) {
                        ulonglong2 wv = wp[q];
                        acc0[2*q]   = ffma2(xa2, wv.x, acc0[2*q]);
                        acc0[2*q+1] = ffma2(xa2, wv.y, acc0[2*q+1]);
                        acc1[2*q]   = ffma2(xb2, wv.x, acc1[2*q]);
                        acc1[2*q+1] = ffma2(xb2, wv.y, acc1[2*q+1]);
                    }
                }
            }
        }
    };

    unsigned tile = blockIdx.x;
    int n  = (tile / 7) & (NN - 1);
    int s  = tile / (7 * NN);
    int h0 = (tile % 7) * TH;
    int cbase = s * KC;

    // Prolog: stage chunk0 of first tile.
    stage_chunk(0, n, h0, cbase);
    cp_commit();                               // pending: {cur.c0}

    while (true) {
        // Prefetch chunk1 of current tile.
        stage_chunk(1, n, h0, cbase + KCS);
        cp_commit();                           // pending: {cur.c0, cur.c1}
        if (tid == 0) s_next = atomicAdd(&g_ctr, 1u);

#pragma unroll
        for (int j = 0; j < 8; j++) { acc0[j] = 0ull; acc1[j] = 0ull; }

        cp_wait<1>();                          // cur.c0 landed
        __syncthreads();
        compute_chunk(0);
        __syncthreads();                       // buf0 free; s_next visible

        unsigned nt = s_next;
        bool have_next = nt < NTILES;
        int nn = 0, nh0 = 0, ncb = 0;
        if (have_next) {
            nn = (nt / 7) & (NN - 1);
            nh0 = (nt % 7) * TH;
            ncb = (nt / (7 * NN)) * KC;
            stage_chunk(0, nn, nh0, ncb);      // prefetch next tile's chunk0
            cp_commit();                       // pending: {cur.c1, next.c0}
            cp_wait<1>();                      // cur.c1 landed
        } else {
            cp_wait<0>();
        }
        __syncthreads();
        compute_chunk(1);

        // Store partials: g_ypart[s][n][o][h*56 + w]
        if (tid < 224) {
            const int h = h0 + r;
            float* yp = &g_ypart[(((size_t)s * NN + n) * COo) * HWSZ + h * WW];
#pragma unroll
            for (int j = 0; j < 8; j++) {
                float lo, hi;
                unpack2(acc0[j], lo, hi);
                yp[(2*j)   * HWSZ + wg] = lo;
                yp[(2*j+1) * HWSZ + wg] = hi;
                unpack2(acc1[j], lo, hi);
                yp[(2*j)   * HWSZ + wg + 28] = lo;
                yp[(2*j+1) * HWSZ + wg + 28] = hi;
            }
        }

        if (!have_next) break;
        n = nn; h0 = nh0; cbase = ncb; s = nt / (7 * NN);
        __syncthreads();   // everyone done reading buf1 before it's re-staged
    }
}

// ---------------------------------------------------------------------------
// Kernel B: reduce 16 split-K partials, apply fused W = w5@w4 (128x16).
// 448 blocks (one per (row, n)); 4 threads per pixel: each reduces 4 of the
// 16 s-partials into smem, then handles 32 of the 128 output channels.
// ---------------------------------------------------------------------------
__global__ __launch_bounds__(224)
void epilogue_kernel(float* __restrict__ out) {
    __shared__ float Wsh[CC * COo];
    __shared__ float ysh[COo][4][57];   // [c][q][px]
    const int tid = threadIdx.x;
    for (int i = tid; i < CC * COo; i += 224) Wsh[i] = g_W[i];

    const int n  = blockIdx.y;
    const int h  = blockIdx.x;
    const int px = tid % 56;
    const int q  = tid / 56;          // 0..3
    const int p  = h * WW + px;
    __syncthreads();

    // partial reduction: each thread sums 4 of the 16 s-slices for all 16 c
#pragma unroll
    for (int c = 0; c < COo; c++) {
        float v = 0.0f;
#pragma unroll
        for (int ss = 0; ss < 4; ss++) {
            int s = q * 4 + ss;
            v += g_ypart[(((size_t)s * NN + n) * COo + c) * HWSZ + p];
        }
        ysh[c][q][px] = v;
    }
    __syncthreads();

    float y[COo];
#pragma unroll
    for (int c = 0; c < COo; c++)
        y[c] = ysh[c][0][px] + ysh[c][1][px] + ysh[c][2][px] + ysh[c][3][px];

    float* outp = out + ((size_t)n * CC) * HWSZ + p;
#pragma unroll 4
    for (int oo = 0; oo < 32; oo++) {
        int o = q * 32 + oo;
        float v = 0.0f;
#pragma unroll
        for (int j = 0; j < COo; j++) v += Wsh[o * COo + j] * y[j];
        outp[(size_t)o * HWSZ] = v;
    }
}

// ---------------------------------------------------------------------------
extern "C" void kernel_launch(void* const* d_in, const int* in_sizes, int n_in,
                              void* d_out, int out_size) {
    const float* x  = (const float*)d_in[0];
    const float* w3 = (const float*)d_in[1];
    const float* w4 = (const float*)d_in[2];
    const float* w5 = (const float*)d_in[3];
    float* out = (float*)d_out;

    prep_kernel<<<144, 512>>>(w3, w4, w5);
    conv_partial_kernel<<<GRID_A, THREADS_A>>>(x);      // 444 persistent blocks
    dim3 gridB(HH, NN);                                 // 448 blocks
    epilogue_kernel<<<gridB, 224>>>(out);
}